// round 14
// baseline (speedup 1.0000x reference)
#include <cuda_runtime.h>
#include <cuda_fp16.h>
#include <cstdint>
#include <math.h>

#define NT 256
#define TILE 16
#define G_OFF    6208         // seg: y1 stage (16 x 388 floats) is the largest occupant
#define SMEM_FLOATS 9344      // + G (16 x 196 floats) = 37376 bytes per CTA (x3 = 112KB/SM)

// A-tile pitches in fp16 elements (row bytes = 16 * odd -> conflict-free ldmatrix)
#define PA0 264
#define PA1 136
#define PA2 72

// Pre-converted fp16 weights (filled by prep_weights). ALL matrices use
// k32-chunk packing: uint4 per lane = B fragments for two m16n8k16 steps.
#define W1S_OFF   0
#define W2S_OFF   114688
#define W1V1_OFF  180224
#define W2V1_OFF  196608
#define W1V2_OFF  212992
#define W2V2_OFF  217088
#define WBUF_SZ   221184
__device__ __half WBUF[WBUF_SZ];

static __device__ __forceinline__ void mma16(float* d, const uint32_t* a,
                                             uint32_t b0, uint32_t b1){
  asm volatile("mma.sync.aligned.m16n8k16.row.col.f32.f16.f16.f32 "
      "{%0,%1,%2,%3}, {%4,%5,%6,%7}, {%8,%9}, {%0,%1,%2,%3};"
      : "+f"(d[0]), "+f"(d[1]), "+f"(d[2]), "+f"(d[3])
      : "r"(a[0]), "r"(a[1]), "r"(a[2]), "r"(a[3]), "r"(b0), "r"(b1));
}

// One ldmatrix.x4 = whole 16x16 fp16 A fragment (a0..a3) for one m16k16 tile.
static __device__ __forceinline__ void ldsm4(uint32_t* r, uint32_t addr){
  asm volatile("ldmatrix.sync.aligned.m8n8.x4.shared.b16 {%0,%1,%2,%3}, [%4];"
      : "=r"(r[0]), "=r"(r[1]), "=r"(r[2]), "=r"(r[3]) : "r"(addr));
}

// ---------------------------------------------------------------------------
// Init kernel: fp16-convert + permute ALL weights into k32-chunk packing:
//   WBUF[off + kc*N*32 + n*32 + w], w = q*8+t ->
//   k = kc*32 + (t>>2)*16 + 2q + (t&1) + (t&2)*4
// ---------------------------------------------------------------------------
__global__ void prep_weights(const float* __restrict__ w1s,
                             const float* __restrict__ w1v1,
                             const float* __restrict__ w1v2,
                             const float* __restrict__ w2s,
                             const float* __restrict__ w2v1,
                             const float* __restrict__ w2v2)
{
  int idx = blockIdx.x * blockDim.x + threadIdx.x;
  if (idx >= WBUF_SZ) return;
  const float* src; int N, loc;
  if      (idx < W2S_OFF)  { src = w1s;  N = 448; loc = idx - W1S_OFF;  }
  else if (idx < W1V1_OFF) { src = w2s;  N = 256; loc = idx - W2S_OFF;  }
  else if (idx < W2V1_OFF) { src = w1v1; N = 128; loc = idx - W1V1_OFF; }
  else if (idx < W1V2_OFF) { src = w2v1; N = 128; loc = idx - W2V1_OFF; }
  else if (idx < W2V2_OFF) { src = w1v2; N = 64;  loc = idx - W1V2_OFF; }
  else                     { src = w2v2; N = 64;  loc = idx - W2V2_OFF; }
  int kc = loc / (N*32); int r = loc - kc*N*32; int n = r >> 5; int w = r & 31;
  int q = w >> 3, t = w & 7;
  int k = kc*32 + (t>>2)*16 + 2*q + (t&1) + (t&2)*4;
  WBUF[idx] = __float2half_rn(src[k*N + n]);
}

// ---------------------------------------------------------------------------
// k32 GEMM: one LDG.128 per (wn, k32 chunk) = B for two m16n8k16 steps.
// DB selects register double-buffer (true) vs burst single-buffer (false).
// A via ldmatrix, parity-indexed, distance-1. No barriers inside.
// ---------------------------------------------------------------------------
template<int K, int N, int WM, int WN, int PA, bool DB>
static __device__ __forceinline__ void run_g32(const __half* __restrict__ gB,
                  uint32_t As_u32, float* acc, int lane, int mi, int nj)
{
  constexpr int NK = K/32;
  const uint4* __restrict__ bp = reinterpret_cast<const uint4*>(gB)
      + (lane & 3) + ((nj*WN)*8 + (lane>>2))*4;
  const int g = lane >> 3, r = lane & 7;
  const uint32_t aaddr = As_u32
      + ((uint32_t)(((mi*WM)*16 + r + (g&1)*8)*PA + (g>>1)*8))*2u;

  uint4    b[DB?2:1][WN];
  uint32_t a[2][WM][4];
  #pragma unroll
  for (int wn=0; wn<WN; wn++) b[0][wn] = __ldg(bp + wn*32);
  #pragma unroll
  for (int wm=0; wm<WM; wm++) ldsm4(a[0][wm], aaddr + wm*(16*PA*2));   // k16 idx 0

  #pragma unroll
  for (int kc=0; kc<NK; kc++){
    const int cur = DB ? (kc & 1) : 0;
    if (DB){
      if (kc+1 < NK){
        #pragma unroll
        for (int wn=0; wn<WN; wn++) b[cur^1][wn] = __ldg(bp + (kc+1)*(N*4) + wn*32);
      }
    } else if (kc > 0){
      #pragma unroll
      for (int wn=0; wn<WN; wn++) b[0][wn] = __ldg(bp + kc*(N*4) + wn*32);
    }
    #pragma unroll
    for (int wm=0; wm<WM; wm++)
      ldsm4(a[1][wm], aaddr + wm*(16*PA*2) + (2*kc+1)*32);
    #pragma unroll
    for (int wn=0; wn<WN; wn++){
      #pragma unroll
      for (int wm=0; wm<WM; wm++)
        mma16(acc+(wm*WN+wn)*4, a[0][wm], b[cur][wn].x, b[cur][wn].y);
    }
    if (kc+1 < NK){
      #pragma unroll
      for (int wm=0; wm<WM; wm++)
        ldsm4(a[0][wm], aaddr + wm*(16*PA*2) + (2*kc+2)*32);
    }
    #pragma unroll
    for (int wn=0; wn<WN; wn++){
      #pragma unroll
      for (int wm=0; wm<WM; wm++)
        mma16(acc+(wm*WN+wn)*4, a[1][wm], b[cur][wn].z, b[cur][wn].w);
    }
  }
}

static __device__ __forceinline__ float sspf(float v, float cssp){
  float sp = fmaxf(v, 0.0f) + log1pf(expf(-fabsf(v)));
  return cssp * (sp - 0.69314718055994531f);
}

__global__ void __launch_bounds__(NT, 3)
resblk_kernel(const float* __restrict__ x, float* __restrict__ out, float cssp)
{
  extern __shared__ float sm[];
  float*  segf = sm;                             // float staging views
  __half* segh = reinterpret_cast<__half*>(sm);  // fp16 A/V tile views
  float*  G    = sm + G_OFF;
  uint32_t sm_u32;
  { uint32_t a; asm("{ .reg .u64 t; cvta.to.shared.u64 t, %1; cvt.u32.u64 %0, t; }"
                    : "=r"(a) : "l"(sm)); sm_u32 = a; }

  const int tid  = threadIdx.x;
  const int lane = tid & 31;
  const int warp = tid >> 5;            // 0..7 = N-group for every GEMM
  const int n0   = blockIdx.x * TILE;
  const float RS128 = 0.08838834764831845f;
  const float RS64  = 0.125f;

  // ================= scalar path =================
  // A0 = fp16(x0 tile)  [16 x 256], pitch PA0  (both sides coalesced)
  for (int t=tid; t<(TILE*256)/4; t+=NT){
    int e=t*4; int ln=e>>8; int col=e&255;
    float4 v = *reinterpret_cast<const float4*>(x + (size_t)(n0+ln)*960 + col);
    *reinterpret_cast<__half2*>(segh + ln*PA0 + col)     = __floats2half2_rn(v.x, v.y);
    *reinterpret_cast<__half2*>(segh + ln*PA0 + col + 2) = __floats2half2_rn(v.z, v.w);
  }
  __syncthreads();
  // s = A0 @ w1s / 16, SSP -> scalars(segh, fp16) + gates(G, fp32)
  {
    float acc[28];
    #pragma unroll
    for (int i=0;i<28;i++) acc[i]=0.f;
    run_g32<256,448,1,7,PA0,false>(&WBUF[W1S_OFF], sm_u32, acc, lane, 0, warp);
    __syncthreads();
    #pragma unroll
    for (int wn=0; wn<7; wn++){
      #pragma unroll
      for (int q=0;q<4;q++){
        int row = (lane>>2) + ((q&2)<<2);
        int col = (warp*7+wn)*8 + ((lane&3)<<1) + (q&1);
        float h = sspf(acc[wn*4+q]*0.0625f, cssp);
        if (col < 256) segh[row*PA0 + col] = __float2half_rn(h);
        else           G[row*196 + (col-256)] = h;
      }
    }
  }
  __syncthreads();
  // y0 = scalars @ w2s / 16 ; stage (fp32) then coalesced residual write
  {
    float acc[16];
    #pragma unroll
    for (int i=0;i<16;i++) acc[i]=0.f;
    run_g32<256,256,1,4,PA0,true>(&WBUF[W2S_OFF], sm_u32, acc, lane, 0, warp);
    __syncthreads();
    #pragma unroll
    for (int wn=0; wn<4; wn++){
      #pragma unroll
      for (int q=0;q<4;q++){
        int row = (lane>>2) + ((q&2)<<2);
        int col = (warp*4+wn)*8 + ((lane&3)<<1) + (q&1);
        segf[row*260 + col] = acc[wn*4+q]*0.0625f;
      }
    }
    __syncthreads();
    for (int t=tid; t<TILE*64; t+=NT){
      int ln=t>>6; int j=(t&63)*4;
      size_t off = (size_t)(n0+ln)*960 + j;
      float4 xr = *reinterpret_cast<const float4*>(x + off);
      float4 yv = *reinterpret_cast<const float4*>(segf + ln*260 + j);
      *reinterpret_cast<float4*>(out + off) =
        make_float4(xr.x+yv.x, xr.y+yv.y, xr.z+yv.z, xr.w+yv.w);
    }
  }
  __syncthreads();

  // ================= v1 path =================
  // A1[c*16+ln][i] = fp16(x[ln, 256+3i+c])  [48 x 128], pitch PA1
  // Target-major: each thread packs 8 consecutive i-cols -> one STS.128.
  for (int t=tid; t<48*16; t+=NT){
    int row = t >> 4; int i3 = (t & 15) << 3;
    int c = row >> 4, ln = row & 15;
    const float* xp = x + (size_t)(n0+ln)*960 + 256 + c + 3*i3;
    __half2 p[4];
    #pragma unroll
    for (int v=0; v<4; v++)
      p[v] = __floats2half2_rn(xp[6*v], xp[6*v+3]);
    *reinterpret_cast<uint4*>(segh + row*PA1 + i3) = *reinterpret_cast<uint4*>(p);
  }
  __syncthreads();
  // V1 = A1 @ w1v1 * rs128, gated, in place (fp16)
  {
    float acc[24];
    #pragma unroll
    for (int i=0;i<24;i++) acc[i]=0.f;
    run_g32<128,128,3,2,PA1,true>(&WBUF[W1V1_OFF], sm_u32, acc, lane, 0, warp);
    __syncthreads();
    #pragma unroll
    for (int wm=0; wm<3; wm++){
      #pragma unroll
      for (int wn=0; wn<2; wn++){
        #pragma unroll
        for (int q=0;q<4;q++){
          int row = wm*16 + (lane>>2) + ((q&2)<<2);
          int col = (warp*2+wn)*8 + ((lane&3)<<1) + (q&1);
          float g = G[(row&15)*196 + col];
          segh[row*PA1 + col] = __float2half_rn(acc[(wm*2+wn)*4+q]*RS128*g);
        }
      }
    }
  }
  __syncthreads();
  // Y1 = V1 @ w2v1 * rs128 -> stage [n][3o+c] (fp32) -> coalesced residual write
  {
    float acc[24];
    #pragma unroll
    for (int i=0;i<24;i++) acc[i]=0.f;
    run_g32<128,128,3,2,PA1,true>(&WBUF[W2V1_OFF], sm_u32, acc, lane, 0, warp);
    __syncthreads();
    #pragma unroll
    for (int wm=0; wm<3; wm++){
      #pragma unroll
      for (int wn=0; wn<2; wn++){
        #pragma unroll
        for (int q=0;q<4;q++){
          int row = wm*16 + (lane>>2) + ((q&2)<<2);
          int col = (warp*2+wn)*8 + ((lane&3)<<1) + (q&1);
          int n = row & 15; int c = row >> 4;
          segf[n*388 + 3*col + c] = acc[(wm*2+wn)*4+q]*RS128;
        }
      }
    }
    __syncthreads();
    for (int t=tid; t<TILE*96; t+=NT){
      int ln=t/96; int j=(t-ln*96)*4;
      size_t off = (size_t)(n0+ln)*960 + 256 + j;
      float4 xr = *reinterpret_cast<const float4*>(x + off);
      float4 yv = *reinterpret_cast<const float4*>(segf + ln*388 + j);
      *reinterpret_cast<float4*>(out + off) =
        make_float4(xr.x+yv.x, xr.y+yv.y, xr.z+yv.z, xr.w+yv.w);
    }
  }
  __syncthreads();

  // ================= v2 path =================
  // A2[c*16+ln][i] = fp16(x[ln, 640+5i+c])  [80 x 64], pitch PA2
  // Target-major: each thread packs 8 consecutive i-cols -> one STS.128.
  for (int t=tid; t<80*8; t+=NT){
    int row = t >> 3; int i5 = (t & 7) << 3;
    int c = row >> 4, ln = row & 15;
    const float* xp = x + (size_t)(n0+ln)*960 + 640 + c + 5*i5;
    __half2 p[4];
    #pragma unroll
    for (int v=0; v<4; v++)
      p[v] = __floats2half2_rn(xp[10*v], xp[10*v+5]);
    *reinterpret_cast<uint4*>(segh + row*PA2 + i5) = *reinterpret_cast<uint4*>(p);
  }
  __syncthreads();
  // V2 = A2 @ w1v2 * rs64, gated, in place (fp16)
  {
    float acc[20];
    #pragma unroll
    for (int i=0;i<20;i++) acc[i]=0.f;
    run_g32<64,64,5,1,PA2,true>(&WBUF[W1V2_OFF], sm_u32, acc, lane, 0, warp);
    __syncthreads();
    #pragma unroll
    for (int wm=0; wm<5; wm++){
      #pragma unroll
      for (int q=0;q<4;q++){
        int row = wm*16 + (lane>>2) + ((q&2)<<2);
        int col = warp*8 + ((lane&3)<<1) + (q&1);
        float g = G[(row&15)*196 + 128 + col];
        segh[row*PA2 + col] = __float2half_rn(acc[wm*4+q]*RS64*g);
      }
    }
  }
  __syncthreads();
  // Y2 = V2 @ w2v2 * rs64 -> stage [n][5o+c] (fp32) -> coalesced residual write
  {
    float acc[20];
    #pragma unroll
    for (int i=0;i<20;i++) acc[i]=0.f;
    run_g32<64,64,5,1,PA2,true>(&WBUF[W2V2_OFF], sm_u32, acc, lane, 0, warp);
    __syncthreads();
    #pragma unroll
    for (int wm=0; wm<5; wm++){
      #pragma unroll
      for (int q=0;q<4;q++){
        int row = wm*16 + (lane>>2) + ((q&2)<<2);
        int col = warp*8 + ((lane&3)<<1) + (q&1);
        int n = row & 15; int c = row >> 4;
        segf[n*324 + 5*col + c] = acc[wm*4+q]*RS64;
      }
    }
    __syncthreads();
    for (int t=tid; t<TILE*80; t+=NT){
      int ln=t/80; int j=(t-ln*80)*4;
      size_t off = (size_t)(n0+ln)*960 + 640 + j;
      float4 xr = *reinterpret_cast<const float4*>(x + off);
      float4 yv = *reinterpret_cast<const float4*>(segf + ln*324 + j);
      *reinterpret_cast<float4*>(out + off) =
        make_float4(xr.x+yv.x, xr.y+yv.y, xr.z+yv.z, xr.w+yv.w);
    }
  }
}

static double compute_cssp_host(){
  const int NP = 200001;
  const double LOG2 = 0.6931471805599453094172321214581766;
  double s = 0.0;
  for (int i=0;i<NP;i++){
    double z = -10.0 + (20.0 * i) / (NP - 1);
    double phi = exp(-0.5*z*z) / sqrt(2.0*3.14159265358979323846);
    double sp  = (z > 0.0) ? (z + log1p(exp(-z))) : log1p(exp(z));
    double f   = sp - LOG2;
    double w   = (i==0 || i==NP-1) ? 0.5 : 1.0;
    s += w * f * f * phi;
  }
  s *= 20.0 / (NP - 1);
  return 1.0 / sqrt(s);
}

extern "C" void kernel_launch(void* const* d_in, const int* in_sizes, int n_in,
                              void* d_out, int out_size) {
  const float* x    = (const float*)d_in[0];
  const float* w1s  = (const float*)d_in[1];
  const float* w1v1 = (const float*)d_in[2];
  const float* w1v2 = (const float*)d_in[3];
  const float* w2s  = (const float*)d_in[4];
  const float* w2v1 = (const float*)d_in[5];
  const float* w2v2 = (const float*)d_in[6];
  float* out = (float*)d_out;

  int n = in_sizes[0] / 960;

  static bool attr_done = false;
  if (!attr_done){
    cudaFuncSetAttribute(resblk_kernel,
        cudaFuncAttributeMaxDynamicSharedMemorySize, SMEM_FLOATS*4);
    attr_done = true;
  }
  static const float cssp = (float)compute_cssp_host();

  prep_weights<<<(WBUF_SZ + NT - 1)/NT, NT>>>(w1s, w1v1, w1v2, w2s, w2v1, w2v2);
  resblk_kernel<<<n/TILE, NT, SMEM_FLOATS*4>>>(x, out, cssp);
}

// round 15
// speedup vs baseline: 1.0874x; 1.0874x over previous
#include <cuda_runtime.h>
#include <cuda_fp16.h>
#include <cstdint>
#include <math.h>

#define NT 256
#define TILE 16
#define G_OFF    6208         // seg: y1 stage (16 x 388 floats) is the largest occupant
#define SMEM_FLOATS 9344      // + G (16 x 196 floats) = 37376 bytes per CTA (x3 = 112KB/SM)

// A-tile pitches in fp16 elements (row bytes = 16 * odd -> conflict-free ldmatrix)
#define PA0 264
#define PA1 136
#define PA2 72

// Pre-converted fp16 weights (filled by prep_weights). ALL matrices use
// k32-chunk packing: uint4 per lane = B fragments for two m16n8k16 steps.
#define W1S_OFF   0
#define W2S_OFF   114688
#define W1V1_OFF  180224
#define W2V1_OFF  196608
#define W1V2_OFF  212992
#define W2V2_OFF  217088
#define WBUF_SZ   221184
__device__ __half WBUF[WBUF_SZ];

static __device__ __forceinline__ void mma16(float* d, const uint32_t* a,
                                             uint32_t b0, uint32_t b1){
  asm volatile("mma.sync.aligned.m16n8k16.row.col.f32.f16.f16.f32 "
      "{%0,%1,%2,%3}, {%4,%5,%6,%7}, {%8,%9}, {%0,%1,%2,%3};"
      : "+f"(d[0]), "+f"(d[1]), "+f"(d[2]), "+f"(d[3])
      : "r"(a[0]), "r"(a[1]), "r"(a[2]), "r"(a[3]), "r"(b0), "r"(b1));
}

// One ldmatrix.x4 = whole 16x16 fp16 A fragment (a0..a3) for one m16k16 tile.
static __device__ __forceinline__ void ldsm4(uint32_t* r, uint32_t addr){
  asm volatile("ldmatrix.sync.aligned.m8n8.x4.shared.b16 {%0,%1,%2,%3}, [%4];"
      : "=r"(r[0]), "=r"(r[1]), "=r"(r[2]), "=r"(r[3]) : "r"(addr));
}

// ---------------------------------------------------------------------------
// Init kernel: fp16-convert + permute ALL weights into k32-chunk packing:
//   WBUF[off + kc*N*32 + n*32 + w], w = q*8+t ->
//   k = kc*32 + (t>>2)*16 + 2q + (t&1) + (t&2)*4
// ---------------------------------------------------------------------------
__global__ void prep_weights(const float* __restrict__ w1s,
                             const float* __restrict__ w1v1,
                             const float* __restrict__ w1v2,
                             const float* __restrict__ w2s,
                             const float* __restrict__ w2v1,
                             const float* __restrict__ w2v2)
{
  int idx = blockIdx.x * blockDim.x + threadIdx.x;
  if (idx >= WBUF_SZ) return;
  const float* src; int N, loc;
  if      (idx < W2S_OFF)  { src = w1s;  N = 448; loc = idx - W1S_OFF;  }
  else if (idx < W1V1_OFF) { src = w2s;  N = 256; loc = idx - W2S_OFF;  }
  else if (idx < W2V1_OFF) { src = w1v1; N = 128; loc = idx - W1V1_OFF; }
  else if (idx < W1V2_OFF) { src = w2v1; N = 128; loc = idx - W2V1_OFF; }
  else if (idx < W2V2_OFF) { src = w1v2; N = 64;  loc = idx - W1V2_OFF; }
  else                     { src = w2v2; N = 64;  loc = idx - W2V2_OFF; }
  int kc = loc / (N*32); int r = loc - kc*N*32; int n = r >> 5; int w = r & 31;
  int q = w >> 3, t = w & 7;
  int k = kc*32 + (t>>2)*16 + 2*q + (t&1) + (t&2)*4;
  WBUF[idx] = __float2half_rn(src[k*N + n]);
}

// ---------------------------------------------------------------------------
// k32 GEMM: one LDG.128 per (wn, k32 chunk) = B for two m16n8k16 steps.
// DB selects register double-buffer (true) vs burst single-buffer (false).
// A via ldmatrix, parity-indexed, distance-1. No barriers inside.
// ---------------------------------------------------------------------------
template<int K, int N, int WM, int WN, int PA, bool DB>
static __device__ __forceinline__ void run_g32(const __half* __restrict__ gB,
                  uint32_t As_u32, float* acc, int lane, int mi, int nj)
{
  constexpr int NK = K/32;
  const uint4* __restrict__ bp = reinterpret_cast<const uint4*>(gB)
      + (lane & 3) + ((nj*WN)*8 + (lane>>2))*4;
  const int g = lane >> 3, r = lane & 7;
  const uint32_t aaddr = As_u32
      + ((uint32_t)(((mi*WM)*16 + r + (g&1)*8)*PA + (g>>1)*8))*2u;

  uint4    b[DB?2:1][WN];
  uint32_t a[2][WM][4];
  #pragma unroll
  for (int wn=0; wn<WN; wn++) b[0][wn] = __ldg(bp + wn*32);
  #pragma unroll
  for (int wm=0; wm<WM; wm++) ldsm4(a[0][wm], aaddr + wm*(16*PA*2));   // k16 idx 0

  #pragma unroll
  for (int kc=0; kc<NK; kc++){
    const int cur = DB ? (kc & 1) : 0;
    if (DB){
      if (kc+1 < NK){
        #pragma unroll
        for (int wn=0; wn<WN; wn++) b[cur^1][wn] = __ldg(bp + (kc+1)*(N*4) + wn*32);
      }
    } else if (kc > 0){
      #pragma unroll
      for (int wn=0; wn<WN; wn++) b[0][wn] = __ldg(bp + kc*(N*4) + wn*32);
    }
    #pragma unroll
    for (int wm=0; wm<WM; wm++)
      ldsm4(a[1][wm], aaddr + wm*(16*PA*2) + (2*kc+1)*32);
    #pragma unroll
    for (int wn=0; wn<WN; wn++){
      #pragma unroll
      for (int wm=0; wm<WM; wm++)
        mma16(acc+(wm*WN+wn)*4, a[0][wm], b[cur][wn].x, b[cur][wn].y);
    }
    if (kc+1 < NK){
      #pragma unroll
      for (int wm=0; wm<WM; wm++)
        ldsm4(a[0][wm], aaddr + wm*(16*PA*2) + (2*kc+2)*32);
    }
    #pragma unroll
    for (int wn=0; wn<WN; wn++){
      #pragma unroll
      for (int wm=0; wm<WM; wm++)
        mma16(acc+(wm*WN+wn)*4, a[1][wm], b[cur][wn].z, b[cur][wn].w);
    }
  }
}

static __device__ __forceinline__ float sspf(float v, float cssp){
  float sp = fmaxf(v, 0.0f) + log1pf(expf(-fabsf(v)));
  return cssp * (sp - 0.69314718055994531f);
}

__global__ void __launch_bounds__(NT, 3)
resblk_kernel(const float* __restrict__ x, float* __restrict__ out, float cssp)
{
  extern __shared__ float sm[];
  float*  segf = sm;                             // float staging views
  __half* segh = reinterpret_cast<__half*>(sm);  // fp16 A/V tile views
  float*  G    = sm + G_OFF;
  uint32_t sm_u32;
  { uint32_t a; asm("{ .reg .u64 t; cvta.to.shared.u64 t, %1; cvt.u32.u64 %0, t; }"
                    : "=r"(a) : "l"(sm)); sm_u32 = a; }

  const int tid  = threadIdx.x;
  const int lane = tid & 31;
  const int warp = tid >> 5;            // 0..7 = N-group for every GEMM
  const int n0   = blockIdx.x * TILE;
  const float RS128 = 0.08838834764831845f;
  const float RS64  = 0.125f;

  // ================= scalar path =================
  // A0 = fp16(x0 tile)  [16 x 256], pitch PA0 (STS.64 packed)
  for (int t=tid; t<(TILE*256)/4; t+=NT){
    int e=t*4; int ln=e>>8; int col=e&255;
    float4 v = *reinterpret_cast<const float4*>(x + (size_t)(n0+ln)*960 + col);
    __half2 p0 = __floats2half2_rn(v.x, v.y);
    __half2 p1 = __floats2half2_rn(v.z, v.w);
    uint2 u; u.x = *reinterpret_cast<uint32_t*>(&p0); u.y = *reinterpret_cast<uint32_t*>(&p1);
    *reinterpret_cast<uint2*>(segh + ln*PA0 + col) = u;
  }
  __syncthreads();
  // s = A0 @ w1s / 16, SSP -> scalars(segh, fp16) + gates(G, fp32)  [paired stores]
  {
    float acc[28];
    #pragma unroll
    for (int i=0;i<28;i++) acc[i]=0.f;
    run_g32<256,448,1,7,PA0,false>(&WBUF[W1S_OFF], sm_u32, acc, lane, 0, warp);
    __syncthreads();
    #pragma unroll
    for (int wn=0; wn<7; wn++){
      int col = (warp*7+wn)*8 + ((lane&3)<<1);
      #pragma unroll
      for (int h=0; h<2; h++){
        int row = (lane>>2) + h*8;
        float h0 = sspf(acc[wn*4+2*h+0]*0.0625f, cssp);
        float h1 = sspf(acc[wn*4+2*h+1]*0.0625f, cssp);
        if (col < 256)
          *reinterpret_cast<__half2*>(segh + row*PA0 + col) = __floats2half2_rn(h0, h1);
        else
          *reinterpret_cast<float2*>(G + row*196 + (col-256)) = make_float2(h0, h1);
      }
    }
  }
  __syncthreads();
  // y0 = scalars @ w2s / 16 ; stage (float2) then coalesced residual write
  {
    float acc[16];
    #pragma unroll
    for (int i=0;i<16;i++) acc[i]=0.f;
    run_g32<256,256,1,4,PA0,true>(&WBUF[W2S_OFF], sm_u32, acc, lane, 0, warp);
    __syncthreads();
    #pragma unroll
    for (int wn=0; wn<4; wn++){
      int col = (warp*4+wn)*8 + ((lane&3)<<1);
      #pragma unroll
      for (int h=0; h<2; h++){
        int row = (lane>>2) + h*8;
        *reinterpret_cast<float2*>(segf + row*260 + col) =
          make_float2(acc[wn*4+2*h]*0.0625f, acc[wn*4+2*h+1]*0.0625f);
      }
    }
    __syncthreads();
    for (int t=tid; t<TILE*64; t+=NT){
      int ln=t>>6; int j=(t&63)*4;
      size_t off = (size_t)(n0+ln)*960 + j;
      float4 xr = *reinterpret_cast<const float4*>(x + off);
      float4 yv = *reinterpret_cast<const float4*>(segf + ln*260 + j);
      *reinterpret_cast<float4*>(out + off) =
        make_float4(xr.x+yv.x, xr.y+yv.y, xr.z+yv.z, xr.w+yv.w);
    }
  }
  __syncthreads();

  // ================= v1 path =================
  // A1[c*16+ln][i] = fp16(x[ln, 256+3i+c])  [48 x 128], pitch PA1  (R13 proven)
  for (int t=tid; t<(TILE*384)/4; t+=NT){
    int e=t*4; int ln=e/384; int j=e-ln*384;
    float4 v = *reinterpret_cast<const float4*>(x + (size_t)(n0+ln)*960 + 256 + j);
    float vv[4]={v.x,v.y,v.z,v.w};
    #pragma unroll
    for (int q=0;q<4;q++){
      int jj=j+q; int i3=jj/3; int c=jj-i3*3;
      segh[(c*16+ln)*PA1 + i3] = __float2half_rn(vv[q]);
    }
  }
  __syncthreads();
  // V1 = A1 @ w1v1 * rs128, gated, in place (half2 stores, float2 G reads)
  {
    float acc[24];
    #pragma unroll
    for (int i=0;i<24;i++) acc[i]=0.f;
    run_g32<128,128,3,2,PA1,true>(&WBUF[W1V1_OFF], sm_u32, acc, lane, 0, warp);
    __syncthreads();
    #pragma unroll
    for (int wm=0; wm<3; wm++){
      #pragma unroll
      for (int wn=0; wn<2; wn++){
        int col = (warp*2+wn)*8 + ((lane&3)<<1);
        #pragma unroll
        for (int h=0; h<2; h++){
          int row = wm*16 + (lane>>2) + h*8;
          float2 g2 = *reinterpret_cast<const float2*>(G + (row&15)*196 + col);
          *reinterpret_cast<__half2*>(segh + row*PA1 + col) =
            __floats2half2_rn(acc[(wm*2+wn)*4+2*h]*RS128*g2.x,
                              acc[(wm*2+wn)*4+2*h+1]*RS128*g2.y);
        }
      }
    }
  }
  __syncthreads();
  // Y1 = V1 @ w2v1 * rs128 -> stage [n][3o+c] (scalar, non-adjacent) -> residual
  {
    float acc[24];
    #pragma unroll
    for (int i=0;i<24;i++) acc[i]=0.f;
    run_g32<128,128,3,2,PA1,true>(&WBUF[W2V1_OFF], sm_u32, acc, lane, 0, warp);
    __syncthreads();
    #pragma unroll
    for (int wm=0; wm<3; wm++){
      #pragma unroll
      for (int wn=0; wn<2; wn++){
        #pragma unroll
        for (int q=0;q<4;q++){
          int row = wm*16 + (lane>>2) + ((q&2)<<2);
          int col = (warp*2+wn)*8 + ((lane&3)<<1) + (q&1);
          int n = row & 15; int c = row >> 4;
          segf[n*388 + 3*col + c] = acc[(wm*2+wn)*4+q]*RS128;
        }
      }
    }
    __syncthreads();
    for (int t=tid; t<TILE*96; t+=NT){
      int ln=t/96; int j=(t-ln*96)*4;
      size_t off = (size_t)(n0+ln)*960 + 256 + j;
      float4 xr = *reinterpret_cast<const float4*>(x + off);
      float4 yv = *reinterpret_cast<const float4*>(segf + ln*388 + j);
      *reinterpret_cast<float4*>(out + off) =
        make_float4(xr.x+yv.x, xr.y+yv.y, xr.z+yv.z, xr.w+yv.w);
    }
  }
  __syncthreads();

  // ================= v2 path =================
  // A2[c*16+ln][i] = fp16(x[ln, 640+5i+c])  [80 x 64], pitch PA2  (R13 proven)
  for (int t=tid; t<(TILE*320)/4; t+=NT){
    int e=t*4; int ln=e/320; int j=e-ln*320;
    float4 v = *reinterpret_cast<const float4*>(x + (size_t)(n0+ln)*960 + 640 + j);
    float vv[4]={v.x,v.y,v.z,v.w};
    #pragma unroll
    for (int q=0;q<4;q++){
      int jj=j+q; int i5=jj/5; int c=jj-i5*5;
      segh[(c*16+ln)*PA2 + i5] = __float2half_rn(vv[q]);
    }
  }
  __syncthreads();
  // V2 = A2 @ w1v2 * rs64, gated, in place (half2 stores, float2 G reads)
  {
    float acc[20];
    #pragma unroll
    for (int i=0;i<20;i++) acc[i]=0.f;
    run_g32<64,64,5,1,PA2,true>(&WBUF[W1V2_OFF], sm_u32, acc, lane, 0, warp);
    __syncthreads();
    #pragma unroll
    for (int wm=0; wm<5; wm++){
      int col = warp*8 + ((lane&3)<<1);
      #pragma unroll
      for (int h=0; h<2; h++){
        int row = wm*16 + (lane>>2) + h*8;
        float2 g2 = *reinterpret_cast<const float2*>(G + (row&15)*196 + 128 + col);
        *reinterpret_cast<__half2*>(segh + row*PA2 + col) =
          __floats2half2_rn(acc[wm*4+2*h]*RS64*g2.x, acc[wm*4+2*h+1]*RS64*g2.y);
      }
    }
  }
  __syncthreads();
  // Y2 = V2 @ w2v2 * rs64 -> stage [n][5o+c] (scalar) -> residual
  {
    float acc[20];
    #pragma unroll
    for (int i=0;i<20;i++) acc[i]=0.f;
    run_g32<64,64,5,1,PA2,true>(&WBUF[W2V2_OFF], sm_u32, acc, lane, 0, warp);
    __syncthreads();
    #pragma unroll
    for (int wm=0; wm<5; wm++){
      #pragma unroll
      for (int q=0;q<4;q++){
        int row = wm*16 + (lane>>2) + ((q&2)<<2);
        int col = warp*8 + ((lane&3)<<1) + (q&1);
        int n = row & 15; int c = row >> 4;
        segf[n*324 + 5*col + c] = acc[wm*4+q]*RS64;
      }
    }
    __syncthreads();
    for (int t=tid; t<TILE*80; t+=NT){
      int ln=t/80; int j=(t-ln*80)*4;
      size_t off = (size_t)(n0+ln)*960 + 640 + j;
      float4 xr = *reinterpret_cast<const float4*>(x + off);
      float4 yv = *reinterpret_cast<const float4*>(segf + ln*324 + j);
      *reinterpret_cast<float4*>(out + off) =
        make_float4(xr.x+yv.x, xr.y+yv.y, xr.z+yv.z, xr.w+yv.w);
    }
  }
}

static double compute_cssp_host(){
  const int NP = 200001;
  const double LOG2 = 0.6931471805599453094172321214581766;
  double s = 0.0;
  for (int i=0;i<NP;i++){
    double z = -10.0 + (20.0 * i) / (NP - 1);
    double phi = exp(-0.5*z*z) / sqrt(2.0*3.14159265358979323846);
    double sp  = (z > 0.0) ? (z + log1p(exp(-z))) : log1p(exp(z));
    double f   = sp - LOG2;
    double w   = (i==0 || i==NP-1) ? 0.5 : 1.0;
    s += w * f * f * phi;
  }
  s *= 20.0 / (NP - 1);
  return 1.0 / sqrt(s);
}

extern "C" void kernel_launch(void* const* d_in, const int* in_sizes, int n_in,
                              void* d_out, int out_size) {
  const float* x    = (const float*)d_in[0];
  const float* w1s  = (const float*)d_in[1];
  const float* w1v1 = (const float*)d_in[2];
  const float* w1v2 = (const float*)d_in[3];
  const float* w2s  = (const float*)d_in[4];
  const float* w2v1 = (const float*)d_in[5];
  const float* w2v2 = (const float*)d_in[6];
  float* out = (float*)d_out;

  int n = in_sizes[0] / 960;

  static bool attr_done = false;
  if (!attr_done){
    cudaFuncSetAttribute(resblk_kernel,
        cudaFuncAttributeMaxDynamicSharedMemorySize, SMEM_FLOATS*4);
    attr_done = true;
  }
  static const float cssp = (float)compute_cssp_host();

  prep_weights<<<(WBUF_SZ + NT - 1)/NT, NT>>>(w1s, w1v1, w1v2, w2s, w2v1, w2v2);
  resblk_kernel<<<n/TILE, NT, SMEM_FLOATS*4>>>(x, out, cssp);
}

// round 16
// speedup vs baseline: 1.1804x; 1.0856x over previous
#include <cuda_runtime.h>
#include <cuda_fp16.h>
#include <cstdint>
#include <math.h>

#define NT 256
#define TILE 16
#define G_OFF    6208         // seg: y1 stage (16 x 388 floats) is the largest occupant
#define SMEM_FLOATS 9344      // + G (16 x 196 floats) = 37376 bytes per CTA (x4 = 149.5KB/SM)

// A-tile pitches in fp16 elements (row bytes = 16 * odd -> conflict-free ldmatrix)
#define PA0 264
#define PA1 136
#define PA2 72

// Pre-converted fp16 weights (filled by prep_weights).
// w1s: k16-chunk packing (uint2 per lane). Others: k32-chunk packing (uint4 per lane).
#define W1S_OFF   0
#define W2S_OFF   114688
#define W1V1_OFF  180224
#define W2V1_OFF  196608
#define W1V2_OFF  212992
#define W2V2_OFF  217088
#define WBUF_SZ   221184
__device__ __half WBUF[WBUF_SZ];

static __device__ __forceinline__ void mma16(float* d, const uint32_t* a,
                                             uint32_t b0, uint32_t b1){
  asm volatile("mma.sync.aligned.m16n8k16.row.col.f32.f16.f16.f32 "
      "{%0,%1,%2,%3}, {%4,%5,%6,%7}, {%8,%9}, {%0,%1,%2,%3};"
      : "+f"(d[0]), "+f"(d[1]), "+f"(d[2]), "+f"(d[3])
      : "r"(a[0]), "r"(a[1]), "r"(a[2]), "r"(a[3]), "r"(b0), "r"(b1));
}

// One ldmatrix.x4 = whole 16x16 fp16 A fragment (a0..a3) for one m16k16 tile.
static __device__ __forceinline__ void ldsm4(uint32_t* r, uint32_t addr){
  asm volatile("ldmatrix.sync.aligned.m8n8.x4.shared.b16 {%0,%1,%2,%3}, [%4];"
      : "=r"(r[0]), "=r"(r[1]), "=r"(r[2]), "=r"(r[3]) : "r"(addr));
}

// ---------------------------------------------------------------------------
// Init kernel: fp16-convert + permute.
// w1s (k16): WBUF[kc*N*16 + n*16 + w], w=q*4+j -> k = kc*16 + 2q + (j&1) + (j&2)*4
// others(k32): WBUF[kc*N*32 + n*32 + w], w=q*8+t -> k = kc*32 + (t>>2)*16 + 2q + (t&1) + (t&2)*4
// ---------------------------------------------------------------------------
__global__ void prep_weights(const float* __restrict__ w1s,
                             const float* __restrict__ w1v1,
                             const float* __restrict__ w1v2,
                             const float* __restrict__ w2s,
                             const float* __restrict__ w2v1,
                             const float* __restrict__ w2v2)
{
  int idx = blockIdx.x * blockDim.x + threadIdx.x;
  if (idx >= WBUF_SZ) return;
  const float* src; int N, loc; bool p32 = true;
  if      (idx < W2S_OFF)  { src = w1s;  N = 448; loc = idx - W1S_OFF; p32 = false; }
  else if (idx < W1V1_OFF) { src = w2s;  N = 256; loc = idx - W2S_OFF;  }
  else if (idx < W2V1_OFF) { src = w1v1; N = 128; loc = idx - W1V1_OFF; }
  else if (idx < W1V2_OFF) { src = w2v1; N = 128; loc = idx - W2V1_OFF; }
  else if (idx < W2V2_OFF) { src = w1v2; N = 64;  loc = idx - W1V2_OFF; }
  else                     { src = w2v2; N = 64;  loc = idx - W2V2_OFF; }
  int k, n;
  if (p32){
    int kc = loc / (N*32); int r = loc - kc*N*32; n = r >> 5; int w = r & 31;
    int q = w >> 3, t = w & 7;
    k = kc*32 + (t>>2)*16 + 2*q + (t&1) + (t&2)*4;
  } else {
    int kc = loc / (N*16); int r = loc - kc*N*16; n = r >> 4; int w = r & 15;
    int q = w >> 2, j = w & 3;
    k = kc*16 + 2*q + (j&1) + (j&2)*4;
  }
  WBUF[idx] = __float2half_rn(src[k*N + n]);
}

// ---------------------------------------------------------------------------
// Zero-pipeline GEMMs (occupancy hides latency; minimal live registers).
// k16 variant: B = uint2 burst per k16 chunk (w1s packing).
// ---------------------------------------------------------------------------
template<int K, int N, int WM, int WN, int PA>
static __device__ __forceinline__ void run_l16(const __half* __restrict__ gB,
                  uint32_t As_u32, float* acc, int lane, int nj)
{
  const uint2* __restrict__ bp = reinterpret_cast<const uint2*>(gB)
      + (lane & 3) + ((nj*WN)*8 + (lane>>2))*4;
  const int g = lane >> 3, r = lane & 7;
  const uint32_t aaddr = As_u32
      + ((uint32_t)((r + (g&1)*8)*PA + (g>>1)*8))*2u;

  #pragma unroll
  for (int kc=0; kc<K/16; kc++){
    uint2 b[WN];
    #pragma unroll
    for (int wn=0; wn<WN; wn++) b[wn] = __ldg(bp + kc*(N*4) + wn*32);
    uint32_t a[WM][4];
    #pragma unroll
    for (int wm=0; wm<WM; wm++) ldsm4(a[wm], aaddr + wm*(16*PA*2) + kc*32);
    #pragma unroll
    for (int wn=0; wn<WN; wn++){
      #pragma unroll
      for (int wm=0; wm<WM; wm++)
        mma16(acc+(wm*WN+wn)*4, a[wm], b[wn].x, b[wn].y);
    }
  }
}

// k32 variant: B = uint4 burst per k32 chunk; A loaded per k16 sub-step.
template<int K, int N, int WM, int WN, int PA>
static __device__ __forceinline__ void run_l32(const __half* __restrict__ gB,
                  uint32_t As_u32, float* acc, int lane, int nj)
{
  const uint4* __restrict__ bp = reinterpret_cast<const uint4*>(gB)
      + (lane & 3) + ((nj*WN)*8 + (lane>>2))*4;
  const int g = lane >> 3, r = lane & 7;
  const uint32_t aaddr = As_u32
      + ((uint32_t)((r + (g&1)*8)*PA + (g>>1)*8))*2u;

  #pragma unroll
  for (int kc=0; kc<K/32; kc++){
    uint4 b[WN];
    #pragma unroll
    for (int wn=0; wn<WN; wn++) b[wn] = __ldg(bp + kc*(N*4) + wn*32);
    {
      uint32_t a[WM][4];
      #pragma unroll
      for (int wm=0; wm<WM; wm++) ldsm4(a[wm], aaddr + wm*(16*PA*2) + (2*kc)*32);
      #pragma unroll
      for (int wn=0; wn<WN; wn++){
        #pragma unroll
        for (int wm=0; wm<WM; wm++)
          mma16(acc+(wm*WN+wn)*4, a[wm], b[wn].x, b[wn].y);
      }
    }
    {
      uint32_t a[WM][4];
      #pragma unroll
      for (int wm=0; wm<WM; wm++) ldsm4(a[wm], aaddr + wm*(16*PA*2) + (2*kc+1)*32);
      #pragma unroll
      for (int wn=0; wn<WN; wn++){
        #pragma unroll
        for (int wm=0; wm<WM; wm++)
          mma16(acc+(wm*WN+wn)*4, a[wm], b[wn].z, b[wn].w);
      }
    }
  }
}

static __device__ __forceinline__ float sspf(float v, float cssp){
  float sp = fmaxf(v, 0.0f) + log1pf(expf(-fabsf(v)));
  return cssp * (sp - 0.69314718055994531f);
}

__global__ void __launch_bounds__(NT, 4)
resblk_kernel(const float* __restrict__ x, float* __restrict__ out, float cssp)
{
  extern __shared__ float sm[];
  float*  segf = sm;                             // float staging views
  __half* segh = reinterpret_cast<__half*>(sm);  // fp16 A/V tile views
  float*  G    = sm + G_OFF;
  uint32_t sm_u32;
  { uint32_t a; asm("{ .reg .u64 t; cvta.to.shared.u64 t, %1; cvt.u32.u64 %0, t; }"
                    : "=r"(a) : "l"(sm)); sm_u32 = a; }

  const int tid  = threadIdx.x;
  const int lane = tid & 31;
  const int warp = tid >> 5;            // 0..7 = N-group for every GEMM
  const int n0   = blockIdx.x * TILE;
  const float RS128 = 0.08838834764831845f;
  const float RS64  = 0.125f;

  // ================= scalar path =================
  // A0 = fp16(x0 tile)  [16 x 256], pitch PA0 (STS.64 packed)
  for (int t=tid; t<(TILE*256)/4; t+=NT){
    int e=t*4; int ln=e>>8; int col=e&255;
    float4 v = *reinterpret_cast<const float4*>(x + (size_t)(n0+ln)*960 + col);
    __half2 p0 = __floats2half2_rn(v.x, v.y);
    __half2 p1 = __floats2half2_rn(v.z, v.w);
    uint2 u; u.x = *reinterpret_cast<uint32_t*>(&p0); u.y = *reinterpret_cast<uint32_t*>(&p1);
    *reinterpret_cast<uint2*>(segh + ln*PA0 + col) = u;
  }
  __syncthreads();
  // s = A0 @ w1s / 16, SSP -> scalars(segh, fp16) + gates(G, fp32)  [paired stores]
  {
    float acc[28];
    #pragma unroll
    for (int i=0;i<28;i++) acc[i]=0.f;
    run_l16<256,448,1,7,PA0>(&WBUF[W1S_OFF], sm_u32, acc, lane, warp);
    __syncthreads();
    #pragma unroll
    for (int wn=0; wn<7; wn++){
      int col = (warp*7+wn)*8 + ((lane&3)<<1);
      #pragma unroll
      for (int h=0; h<2; h++){
        int row = (lane>>2) + h*8;
        float h0 = sspf(acc[wn*4+2*h+0]*0.0625f, cssp);
        float h1 = sspf(acc[wn*4+2*h+1]*0.0625f, cssp);
        if (col < 256)
          *reinterpret_cast<__half2*>(segh + row*PA0 + col) = __floats2half2_rn(h0, h1);
        else
          *reinterpret_cast<float2*>(G + row*196 + (col-256)) = make_float2(h0, h1);
      }
    }
  }
  __syncthreads();
  // y0 = scalars @ w2s / 16 ; stage (float2) then coalesced residual write
  {
    float acc[16];
    #pragma unroll
    for (int i=0;i<16;i++) acc[i]=0.f;
    run_l32<256,256,1,4,PA0>(&WBUF[W2S_OFF], sm_u32, acc, lane, warp);
    __syncthreads();
    #pragma unroll
    for (int wn=0; wn<4; wn++){
      int col = (warp*4+wn)*8 + ((lane&3)<<1);
      #pragma unroll
      for (int h=0; h<2; h++){
        int row = (lane>>2) + h*8;
        *reinterpret_cast<float2*>(segf + row*260 + col) =
          make_float2(acc[wn*4+2*h]*0.0625f, acc[wn*4+2*h+1]*0.0625f);
      }
    }
    __syncthreads();
    for (int t=tid; t<TILE*64; t+=NT){
      int ln=t>>6; int j=(t&63)*4;
      size_t off = (size_t)(n0+ln)*960 + j;
      float4 xr = *reinterpret_cast<const float4*>(x + off);
      float4 yv = *reinterpret_cast<const float4*>(segf + ln*260 + j);
      *reinterpret_cast<float4*>(out + off) =
        make_float4(xr.x+yv.x, xr.y+yv.y, xr.z+yv.z, xr.w+yv.w);
    }
  }
  __syncthreads();

  // ================= v1 path =================
  // A1[c*16+ln][i] = fp16(x[ln, 256+3i+c])  [48 x 128], pitch PA1  (R13 proven)
  for (int t=tid; t<(TILE*384)/4; t+=NT){
    int e=t*4; int ln=e/384; int j=e-ln*384;
    float4 v = *reinterpret_cast<const float4*>(x + (size_t)(n0+ln)*960 + 256 + j);
    float vv[4]={v.x,v.y,v.z,v.w};
    #pragma unroll
    for (int q=0;q<4;q++){
      int jj=j+q; int i3=jj/3; int c=jj-i3*3;
      segh[(c*16+ln)*PA1 + i3] = __float2half_rn(vv[q]);
    }
  }
  __syncthreads();
  // V1 = A1 @ w1v1 * rs128, gated, in place (half2 stores, float2 G reads)
  {
    float acc[24];
    #pragma unroll
    for (int i=0;i<24;i++) acc[i]=0.f;
    run_l32<128,128,3,2,PA1>(&WBUF[W1V1_OFF], sm_u32, acc, lane, warp);
    __syncthreads();
    #pragma unroll
    for (int wm=0; wm<3; wm++){
      #pragma unroll
      for (int wn=0; wn<2; wn++){
        int col = (warp*2+wn)*8 + ((lane&3)<<1);
        #pragma unroll
        for (int h=0; h<2; h++){
          int row = wm*16 + (lane>>2) + h*8;
          float2 g2 = *reinterpret_cast<const float2*>(G + (row&15)*196 + col);
          *reinterpret_cast<__half2*>(segh + row*PA1 + col) =
            __floats2half2_rn(acc[(wm*2+wn)*4+2*h]*RS128*g2.x,
                              acc[(wm*2+wn)*4+2*h+1]*RS128*g2.y);
        }
      }
    }
  }
  __syncthreads();
  // Y1 = V1 @ w2v1 * rs128 -> stage [n][3o+c] (scalar, non-adjacent) -> residual
  {
    float acc[24];
    #pragma unroll
    for (int i=0;i<24;i++) acc[i]=0.f;
    run_l32<128,128,3,2,PA1>(&WBUF[W2V1_OFF], sm_u32, acc, lane, warp);
    __syncthreads();
    #pragma unroll
    for (int wm=0; wm<3; wm++){
      #pragma unroll
      for (int wn=0; wn<2; wn++){
        #pragma unroll
        for (int q=0;q<4;q++){
          int row = wm*16 + (lane>>2) + ((q&2)<<2);
          int col = (warp*2+wn)*8 + ((lane&3)<<1) + (q&1);
          int n = row & 15; int c = row >> 4;
          segf[n*388 + 3*col + c] = acc[(wm*2+wn)*4+q]*RS128;
        }
      }
    }
    __syncthreads();
    for (int t=tid; t<TILE*96; t+=NT){
      int ln=t/96; int j=(t-ln*96)*4;
      size_t off = (size_t)(n0+ln)*960 + 256 + j;
      float4 xr = *reinterpret_cast<const float4*>(x + off);
      float4 yv = *reinterpret_cast<const float4*>(segf + ln*388 + j);
      *reinterpret_cast<float4*>(out + off) =
        make_float4(xr.x+yv.x, xr.y+yv.y, xr.z+yv.z, xr.w+yv.w);
    }
  }
  __syncthreads();

  // ================= v2 path =================
  // A2[c*16+ln][i] = fp16(x[ln, 640+5i+c])  [80 x 64], pitch PA2  (R13 proven)
  for (int t=tid; t<(TILE*320)/4; t+=NT){
    int e=t*4; int ln=e/320; int j=e-ln*320;
    float4 v = *reinterpret_cast<const float4*>(x + (size_t)(n0+ln)*960 + 640 + j);
    float vv[4]={v.x,v.y,v.z,v.w};
    #pragma unroll
    for (int q=0;q<4;q++){
      int jj=j+q; int i5=jj/5; int c=jj-i5*5;
      segh[(c*16+ln)*PA2 + i5] = __float2half_rn(vv[q]);
    }
  }
  __syncthreads();
  // V2 = A2 @ w1v2 * rs64, gated, in place (half2 stores, float2 G reads)
  {
    float acc[20];
    #pragma unroll
    for (int i=0;i<20;i++) acc[i]=0.f;
    run_l32<64,64,5,1,PA2>(&WBUF[W1V2_OFF], sm_u32, acc, lane, warp);
    __syncthreads();
    #pragma unroll
    for (int wm=0; wm<5; wm++){
      int col = warp*8 + ((lane&3)<<1);
      #pragma unroll
      for (int h=0; h<2; h++){
        int row = wm*16 + (lane>>2) + h*8;
        float2 g2 = *reinterpret_cast<const float2*>(G + (row&15)*196 + 128 + col);
        *reinterpret_cast<__half2*>(segh + row*PA2 + col) =
          __floats2half2_rn(acc[wm*4+2*h]*RS64*g2.x, acc[wm*4+2*h+1]*RS64*g2.y);
      }
    }
  }
  __syncthreads();
  // Y2 = V2 @ w2v2 * rs64 -> stage [n][5o+c] (scalar) -> residual
  {
    float acc[20];
    #pragma unroll
    for (int i=0;i<20;i++) acc[i]=0.f;
    run_l32<64,64,5,1,PA2>(&WBUF[W2V2_OFF], sm_u32, acc, lane, warp);
    __syncthreads();
    #pragma unroll
    for (int wm=0; wm<5; wm++){
      #pragma unroll
      for (int q=0;q<4;q++){
        int row = wm*16 + (lane>>2) + ((q&2)<<2);
        int col = warp*8 + ((lane&3)<<1) + (q&1);
        int n = row & 15; int c = row >> 4;
        segf[n*324 + 5*col + c] = acc[wm*4+q]*RS64;
      }
    }
    __syncthreads();
    for (int t=tid; t<TILE*80; t+=NT){
      int ln=t/80; int j=(t-ln*80)*4;
      size_t off = (size_t)(n0+ln)*960 + 640 + j;
      float4 xr = *reinterpret_cast<const float4*>(x + off);
      float4 yv = *reinterpret_cast<const float4*>(segf + ln*324 + j);
      *reinterpret_cast<float4*>(out + off) =
        make_float4(xr.x+yv.x, xr.y+yv.y, xr.z+yv.z, xr.w+yv.w);
    }
  }
}

static double compute_cssp_host(){
  const int NP = 200001;
  const double LOG2 = 0.6931471805599453094172321214581766;
  double s = 0.0;
  for (int i=0;i<NP;i++){
    double z = -10.0 + (20.0 * i) / (NP - 1);
    double phi = exp(-0.5*z*z) / sqrt(2.0*3.14159265358979323846);
    double sp  = (z > 0.0) ? (z + log1p(exp(-z))) : log1p(exp(z));
    double f   = sp - LOG2;
    double w   = (i==0 || i==NP-1) ? 0.5 : 1.0;
    s += w * f * f * phi;
  }
  s *= 20.0 / (NP - 1);
  return 1.0 / sqrt(s);
}

extern "C" void kernel_launch(void* const* d_in, const int* in_sizes, int n_in,
                              void* d_out, int out_size) {
  const float* x    = (const float*)d_in[0];
  const float* w1s  = (const float*)d_in[1];
  const float* w1v1 = (const float*)d_in[2];
  const float* w1v2 = (const float*)d_in[3];
  const float* w2s  = (const float*)d_in[4];
  const float* w2v1 = (const float*)d_in[5];
  const float* w2v2 = (const float*)d_in[6];
  float* out = (float*)d_out;

  int n = in_sizes[0] / 960;

  static bool attr_done = false;
  if (!attr_done){
    cudaFuncSetAttribute(resblk_kernel,
        cudaFuncAttributeMaxDynamicSharedMemorySize, SMEM_FLOATS*4);
    attr_done = true;
  }
  static const float cssp = (float)compute_cssp_host();

  prep_weights<<<(WBUF_SZ + NT - 1)/NT, NT>>>(w1s, w1v1, w1v2, w2s, w2v1, w2v2);
  resblk_kernel<<<n/TILE, NT, SMEM_FLOATS*4>>>(x, out, cssp);
}